// round 4
// baseline (speedup 1.0000x reference)
#include <cuda_runtime.h>
#include <math.h>
#include <stdint.h>

#define BB   64
#define TT   512
#define IND  256
#define OUTD 256
#define HH   1024
#define NCTA 128
#define KB   64
#define KPAD (KB + 4)   // smem stride 68: (68*r + c) % 32 = (4r + c) % 32 -> conflict-free frag loads

// Persistent state (device globals: allocation-free scratch per harness rules)
__device__ float    g_h0[2][BB * HH];
__device__ float    g_h1[2][BB * HH];
__device__ float    g_h1all[TT * BB * HH];   // [t][b][k]
__device__ unsigned g_count;

__global__ void init_kernel(const float* __restrict__ z) {
    int i = blockIdx.x * blockDim.x + threadIdx.x;
    float v = z[i];
    g_h0[0][i] = v;
    g_h1[0][i] = v;
    if (i == 0) g_count = 0u;
}

__device__ __forceinline__ float sigm(float v) { return 1.f / (1.f + __expf(-v)); }

__device__ __forceinline__ float tf32r(float x) {
    uint32_t u;
    asm("cvt.rna.tf32.f32 %0, %1;" : "=r"(u) : "f"(x));
    return __uint_as_float(u);
}

// Software grid barrier. __threadfence (fence.gpu) flushes L1D on sm_103a
// (CCTL.IVALL), so post-barrier loads of g_h* observe remote CTAs' writes.
__device__ __forceinline__ void grid_bar(unsigned target) {
    __syncthreads();
    if (threadIdx.x == 0) {
        __threadfence();
        atomicAdd(&g_count, 1u);
        while (*(volatile unsigned*)&g_count < target) { }
    }
    __syncthreads();
    __threadfence();
}

// One K-chunk (KB wide) of a 64x32 tile via tf32 mma.sync m16n8k8.
// scatter=true: col c -> weight row (c>>3)*1024 + d0 + (c&7)  (4 gates x 8 dims)
// scatter=false: col c -> weight row c0plain + c               (plain GEMM)
__device__ __forceinline__ void mma_chunk(
    const float* __restrict__ A, int ldA,
    const float* __restrict__ W, int ldW,
    int d0, bool scatter, int c0plain,
    float (*As)[KPAD], float (*Bs)[KPAD],
    float cacc[2][4], int tid, int lane, int mrow, int nw)
{
    // Fill A tile: 64 rows x KB k (1024 float4, 4 per thread), tf32-rounded
#pragma unroll
    for (int it = 0; it < 4; it++) {
        int idx = tid + it * 256;
        int r   = idx >> 4;
        int kq  = (idx & 15) << 2;
        float4 v = *(const float4*)(A + (long)r * ldA + kq);
        As[r][kq + 0] = tf32r(v.x);
        As[r][kq + 1] = tf32r(v.y);
        As[r][kq + 2] = tf32r(v.z);
        As[r][kq + 3] = tf32r(v.w);
    }
    // Fill B tile: 32 cols x KB k (512 float4, 2 per thread), tf32-rounded
#pragma unroll
    for (int it = 0; it < 2; it++) {
        int idx = tid + it * 256;
        int c   = idx >> 4;
        int kq  = (idx & 15) << 2;
        int wrow = scatter ? (((c >> 3) << 10) + d0 + (c & 7)) : (c0plain + c);
        float4 v = *(const float4*)(W + (long)wrow * ldW + kq);
        Bs[c][kq + 0] = tf32r(v.x);
        Bs[c][kq + 1] = tf32r(v.y);
        Bs[c][kq + 2] = tf32r(v.z);
        Bs[c][kq + 3] = tf32r(v.w);
    }
    __syncthreads();

    int l4 = lane >> 2, lq = lane & 3;
#pragma unroll
    for (int kc = 0; kc < KB; kc += 8) {
        uint32_t a0 = __float_as_uint(As[mrow + l4][kc + lq]);
        uint32_t a1 = __float_as_uint(As[mrow + 8 + l4][kc + lq]);
        uint32_t a2 = __float_as_uint(As[mrow + l4][kc + 4 + lq]);
        uint32_t a3 = __float_as_uint(As[mrow + 8 + l4][kc + 4 + lq]);
#pragma unroll
        for (int nt = 0; nt < 2; nt++) {
            int n0 = nw + nt * 8;
            uint32_t b0 = __float_as_uint(Bs[n0 + l4][kc + lq]);
            uint32_t b1 = __float_as_uint(Bs[n0 + l4][kc + 4 + lq]);
            asm volatile(
                "mma.sync.aligned.m16n8k8.row.col.f32.tf32.tf32.f32 "
                "{%0,%1,%2,%3}, {%4,%5,%6,%7}, {%8,%9}, {%0,%1,%2,%3};"
                : "+f"(cacc[nt][0]), "+f"(cacc[nt][1]),
                  "+f"(cacc[nt][2]), "+f"(cacc[nt][3])
                : "r"(a0), "r"(a1), "r"(a2), "r"(a3), "r"(b0), "r"(b1));
        }
    }
    __syncthreads();
}

__global__ __launch_bounds__(256) void lstm_persist(
    const float* __restrict__ x,
    const float* __restrict__ Wih0, const float* __restrict__ Whh0,
    const float* __restrict__ bih0, const float* __restrict__ bhh0,
    const float* __restrict__ Wih1, const float* __restrict__ Whh1,
    const float* __restrict__ bih1, const float* __restrict__ bhh1)
{
    __shared__ float As[64][KPAD];
    __shared__ float Bs[32][KPAD];
    __shared__ float bsum0[32], bsum1[32];
    __shared__ float cc0[64][8], cc1[64][8];

    int tid = threadIdx.x, lane = tid & 31, w = tid >> 5;
    int mrow = (w & 3) * 16, nw = (w >> 2) * 16;
    int l4 = lane >> 2, lq = lane & 3;
    int d0 = blockIdx.x * 8;

    if (tid < 32) {
        int g = tid >> 3, j = tid & 7, n = (g << 10) + d0 + j;
        bsum0[tid] = bih0[n] + bhh0[n];
        bsum1[tid] = bih1[n] + bhh1[n];
    }
    {
        int i0 = tid * 2;
        ((float*)cc0)[i0] = 0.f; ((float*)cc0)[i0 + 1] = 0.f;
        ((float*)cc1)[i0] = 0.f; ((float*)cc1)[i0 + 1] = 0.f;
    }
    __syncthreads();

    for (int t = 0; t < TT; t++) {
        int p = t & 1;

        // ---- Phase A: layer 0 ----
        float cA[2][4] = {};
        for (int k0 = 0; k0 < HH; k0 += KB)
            mma_chunk(&g_h0[p][0] + k0, HH, Whh0 + k0, HH, d0, true, 0,
                      As, Bs, cA, tid, lane, mrow, nw);
        if (t > 0)
            for (int k0 = 0; k0 < IND; k0 += KB)
                mma_chunk(x + (t - 1) * IND + k0, TT * IND, Wih0 + k0, IND, d0, true, 0,
                          As, Bs, cA, tid, lane, mrow, nw);

#pragma unroll
        for (int nt = 0; nt < 2; nt++) {
            int n0 = nw + nt * 8;
            As[mrow + l4][n0 + 2 * lq]         = cA[nt][0];
            As[mrow + l4][n0 + 2 * lq + 1]     = cA[nt][1];
            As[mrow + 8 + l4][n0 + 2 * lq]     = cA[nt][2];
            As[mrow + 8 + l4][n0 + 2 * lq + 1] = cA[nt][3];
        }
        __syncthreads();
#pragma unroll
        for (int s = 0; s < 2; s++) {
            int idx = tid * 2 + s, r = idx >> 3, j = idx & 7;
            float gi = As[r][j]      + bsum0[j];
            float gf = As[r][8 + j]  + bsum0[8 + j];
            float gg = As[r][16 + j] + bsum0[16 + j];
            float go = As[r][24 + j] + bsum0[24 + j];
            float c = sigm(gf) * cc0[r][j] + sigm(gi) * tanhf(gg);
            cc0[r][j] = c;
            g_h0[p ^ 1][r * HH + d0 + j] = sigm(go) * tanhf(c);
        }
        grid_bar((unsigned)(2 * t + 1) * NCTA);

        // ---- Phase B: layer 1 ----
        float cB[2][4] = {};
        for (int k0 = 0; k0 < HH; k0 += KB)
            mma_chunk(&g_h0[p ^ 1][0] + k0, HH, Wih1 + k0, HH, d0, true, 0,
                      As, Bs, cB, tid, lane, mrow, nw);
        for (int k0 = 0; k0 < HH; k0 += KB)
            mma_chunk(&g_h1[p][0] + k0, HH, Whh1 + k0, HH, d0, true, 0,
                      As, Bs, cB, tid, lane, mrow, nw);

#pragma unroll
        for (int nt = 0; nt < 2; nt++) {
            int n0 = nw + nt * 8;
            As[mrow + l4][n0 + 2 * lq]         = cB[nt][0];
            As[mrow + l4][n0 + 2 * lq + 1]     = cB[nt][1];
            As[mrow + 8 + l4][n0 + 2 * lq]     = cB[nt][2];
            As[mrow + 8 + l4][n0 + 2 * lq + 1] = cB[nt][3];
        }
        __syncthreads();
#pragma unroll
        for (int s = 0; s < 2; s++) {
            int idx = tid * 2 + s, r = idx >> 3, j = idx & 7;
            float gi = As[r][j]      + bsum1[j];
            float gf = As[r][8 + j]  + bsum1[8 + j];
            float gg = As[r][16 + j] + bsum1[16 + j];
            float go = As[r][24 + j] + bsum1[24 + j];
            float c = sigm(gf) * cc1[r][j] + sigm(gi) * tanhf(gg);
            cc1[r][j] = c;
            float h = sigm(go) * tanhf(c);
            g_h1[p ^ 1][r * HH + d0 + j] = h;
            g_h1all[(long)t * (BB * HH) + r * HH + d0 + j] = h;
        }
        grid_bar((unsigned)(2 * t + 2) * NCTA);
    }
}

// Deferred output projection: out[b,t,:] = h1all[t,b,:] @ Wlin^T + blin (parallel)
__global__ __launch_bounds__(256) void out_kernel(
    const float* __restrict__ Wlin, const float* __restrict__ blin,
    float* __restrict__ out)
{
    __shared__ float As[64][KPAD];
    __shared__ float Bs[32][KPAD];

    int tid = threadIdx.x, lane = tid & 31, w = tid >> 5;
    int mrow = (w & 3) * 16, nw = (w >> 2) * 16;
    int l4 = lane >> 2, lq = lane & 3;
    int m0 = blockIdx.x * 64;
    int c0 = blockIdx.y * 32;

    float cO[2][4] = {};
    for (int k0 = 0; k0 < HH; k0 += KB)
        mma_chunk(g_h1all + (long)m0 * HH + k0, HH, Wlin + k0, HH, 0, false, c0,
                  As, Bs, cO, tid, lane, mrow, nw);

#pragma unroll
    for (int nt = 0; nt < 2; nt++) {
        int n0 = nw + nt * 8;
        int o0 = c0 + n0 + 2 * lq;
        int r0 = m0 + mrow + l4;
        int r1 = r0 + 8;
        int b0i = r0 & 63, t0i = r0 >> 6;
        int b1i = r1 & 63, t1i = r1 >> 6;
        out[(long)b0i * (TT * OUTD) + t0i * OUTD + o0]     = cO[nt][0] + blin[o0];
        out[(long)b0i * (TT * OUTD) + t0i * OUTD + o0 + 1] = cO[nt][1] + blin[o0 + 1];
        out[(long)b1i * (TT * OUTD) + t1i * OUTD + o0]     = cO[nt][2] + blin[o0];
        out[(long)b1i * (TT * OUTD) + t1i * OUTD + o0 + 1] = cO[nt][3] + blin[o0 + 1];
    }
}

extern "C" void kernel_launch(void* const* d_in, const int* in_sizes, int n_in,
                              void* d_out, int out_size)
{
    const float* z    = (const float*)d_in[0];
    const float* x    = (const float*)d_in[1];
    const float* Wih0 = (const float*)d_in[2];
    const float* Whh0 = (const float*)d_in[3];
    const float* bih0 = (const float*)d_in[4];
    const float* bhh0 = (const float*)d_in[5];
    const float* Wih1 = (const float*)d_in[6];
    const float* Whh1 = (const float*)d_in[7];
    const float* bih1 = (const float*)d_in[8];
    const float* bhh1 = (const float*)d_in[9];
    const float* Wlin = (const float*)d_in[10];
    const float* blin = (const float*)d_in[11];
    float* out = (float*)d_out;

    init_kernel<<<64, 1024>>>(z);
    lstm_persist<<<NCTA, 256>>>(x, Wih0, Whh0, bih0, bhh0,
                                Wih1, Whh1, bih1, bhh1);
    out_kernel<<<dim3(TT * BB / 64, OUTD / 32), 256>>>(Wlin, blin, out);
}

// round 5
// speedup vs baseline: 1.9830x; 1.9830x over previous
#include <cuda_runtime.h>
#include <math.h>
#include <stdint.h>

#define BB   64
#define TT   512
#define IND  256
#define OUTD 256
#define HH   1024
#define NCTA 128
#define KB   64
#define KPAD 72   // smem row stride: 8-row frag groups land on distinct 8-bank groups per 16-lane phase

// ---------------- persistent device state (no allocation allowed) ----------------
__device__ float    g_h0p[2][BB * HH];          // packed tf32 h0 ping-pong
__device__ float    g_h1p[2][BB * HH];          // packed tf32 h1 ping-pong
__device__ float    g_h1all[(long)TT * BB * HH];// packed tf32 h1 history [t][b][kp]
__device__ float    g_xp[(long)TT * BB * IND];  // packed tf32 x [t][b][kp]
__device__ float    g_W0h[NCTA * 32 * HH];      // per-CTA scatter-packed weights (tf32)
__device__ float    g_W0x[NCTA * 32 * IND];
__device__ float    g_W1i[NCTA * 32 * HH];
__device__ float    g_W1h[NCTA * 32 * HH];
__device__ float    g_Wlp[(OUTD / 32) * 32 * HH];
__device__ unsigned g_count;

// ---------------- helpers ----------------
__device__ __forceinline__ float sigm(float v) { return 1.f / (1.f + __expf(-v)); }

__device__ __forceinline__ float tf32r(float x) {
    uint32_t u;
    asm("cvt.rna.tf32.f32 %0, %1;" : "=r"(u) : "f"(x));
    return __uint_as_float(u);
}

// k-permutation within each 8-group: position p holds logical k so that the
// mma fragment pair (k, k+4) sits at (2k', 2k'+1) -> one LDS.64 per fragment.
__device__ __forceinline__ int kpos(int k) { return ((k & 3) << 1) | (k >> 2); }   // logical -> packed
__device__ __forceinline__ int kinv(int p) { return ((p & 7) >> 1) + ((p & 1) << 2); } // packed -> logical (within group)

__device__ __forceinline__ void cp_async16(void* dst, const void* src) {
    uint32_t d = (uint32_t)__cvta_generic_to_shared(dst);
    asm volatile("cp.async.cg.shared.global [%0], [%1], 16;\n" :: "r"(d), "l"(src));
}
#define CP_COMMIT() asm volatile("cp.async.commit_group;\n" ::: "memory")
#define CP_WAIT(N)  asm volatile("cp.async.wait_group %0;\n" :: "n"(N) : "memory")

__device__ __forceinline__ unsigned ld_acq(const unsigned* p) {
    unsigned v;
    asm volatile("ld.acquire.gpu.global.u32 %0, [%1];" : "=r"(v) : "l"(p) : "memory");
    return v;
}

// Software grid barrier. Writer side: release via __threadfence; reader spins
// with acquire loads. h travels via L2 (.cg loads), so no L1 flush needed.
__device__ __forceinline__ void grid_bar(unsigned target) {
    __syncthreads();
    if (threadIdx.x == 0) {
        __threadfence();
        atomicAdd(&g_count, 1u);
        while (ld_acq(&g_count) < target) { }
    }
    __syncthreads();
}

// ---------------- init / pack kernels (one-time, off critical path) ----------------
__global__ void init_kernel(const float* __restrict__ z) {
    int i = blockIdx.x * blockDim.x + threadIdx.x;   // over BB*HH
    int k = i & (HH - 1);
    int pk = (i & ~(HH - 1)) + (k & ~7) + kpos(k & 7);
    float v = tf32r(z[i]);
    g_h0p[0][pk] = v;
    g_h1p[0][pk] = v;
    if (i == 0) g_count = 0u;
}

// Scatter-packed gate weights: dst[blk][c][kp], c = gate*8+j -> src row gate*1024 + blk*8 + j.
__global__ void pack_w(const float* __restrict__ src, float* __restrict__ dst, int K, int total) {
    for (int i = blockIdx.x * blockDim.x + threadIdx.x; i < total; i += gridDim.x * blockDim.x) {
        int kp = i % K;
        int c  = (i / K) & 31;
        int blk = i / (K * 32);
        int k = (kp & ~7) + kinv(kp);
        int row = ((c >> 3) << 10) + (blk << 3) + (c & 7);
        dst[i] = tf32r(src[(long)row * K + k]);
    }
}

// Plain packed weights for the output projection: dst[blk][c][kp] <- src[blk*32+c][k]
__global__ void pack_wl(const float* __restrict__ src, float* __restrict__ dst, int K, int total) {
    for (int i = blockIdx.x * blockDim.x + threadIdx.x; i < total; i += gridDim.x * blockDim.x) {
        int kp = i % K;
        int c  = (i / K) & 31;
        int blk = i / (K * 32);
        int k = (kp & ~7) + kinv(kp);
        dst[i] = tf32r(src[(long)(blk * 32 + c) * K + k]);
    }
}

// x: [B][T][IN] -> packed [t][b][kp] tf32
__global__ void pack_x(const float* __restrict__ x) {
    long total = (long)TT * BB * IND;
    for (long i = blockIdx.x * (long)blockDim.x + threadIdx.x; i < total;
         i += (long)gridDim.x * blockDim.x) {
        int kp = (int)(i % IND);
        int b  = (int)((i / IND) & 63);
        int t  = (int)(i / (IND * 64));
        int k = (kp & ~7) + kinv(kp);
        g_xp[i] = tf32r(x[((long)b * TT + t) * IND + k]);
    }
}

// ---------------- GEMM building blocks ----------------
// Fill one chunk: A tile 64 x KB, B tile 32 x KB, via cp.async (L1-bypass).
__device__ __forceinline__ void fill_chunk(
    float (*As)[KPAD], float (*Bs)[KPAD],
    const float* __restrict__ A, int ldA,
    const float* __restrict__ W, int ldW, int tid)
{
    int r  = tid >> 4;
    int kq = (tid & 15) << 2;
#pragma unroll
    for (int it = 0; it < 4; it++) {
        int row = r + it * 16;
        cp_async16(&As[row][kq], A + (long)row * ldA + kq);
    }
#pragma unroll
    for (int it = 0; it < 2; it++) {
        int c = r + it * 16;
        cp_async16(&Bs[c][kq], W + (long)c * ldW + kq);
    }
}

// Compute one chunk: each warp does m16n16 x kKB via tf32 mma.sync, LDS.64 frags.
__device__ __forceinline__ void mma_compute(
    const float (*As)[KPAD], const float (*Bs)[KPAD],
    float cacc[2][4], int mrow, int nw, int l4, int lq)
{
#pragma unroll
    for (int kc = 0; kc < KB; kc += 8) {
        float2 aA = *(const float2*)&As[mrow + l4][kc + 2 * lq];      // (a0, a2)
        float2 aB = *(const float2*)&As[mrow + 8 + l4][kc + 2 * lq];  // (a1, a3)
        uint32_t a0 = __float_as_uint(aA.x), a1 = __float_as_uint(aB.x);
        uint32_t a2 = __float_as_uint(aA.y), a3 = __float_as_uint(aB.y);
#pragma unroll
        for (int nt = 0; nt < 2; nt++) {
            float2 bb = *(const float2*)&Bs[nw + nt * 8 + l4][kc + 2 * lq]; // (b0, b1)
            asm volatile(
                "mma.sync.aligned.m16n8k8.row.col.f32.tf32.tf32.f32 "
                "{%0,%1,%2,%3}, {%4,%5,%6,%7}, {%8,%9}, {%0,%1,%2,%3};"
                : "+f"(cacc[nt][0]), "+f"(cacc[nt][1]),
                  "+f"(cacc[nt][2]), "+f"(cacc[nt][3])
                : "r"(a0), "r"(a1), "r"(a2), "r"(a3),
                  "r"(__float_as_uint(bb.x)), "r"(__float_as_uint(bb.y)));
        }
    }
}

// Double-buffered pipelined GEMM over up to two (A, W) segments.
__device__ __forceinline__ void run_gemm(
    float (*As)[KPAD], float (*Bs)[KPAD],
    const float* a0, int lda0, const float* w0, int lw0, int n0c,
    const float* a1, int lda1, const float* w1, int lw1, int n1c,
    float cacc[2][4], int tid, int mrow, int nw, int l4, int lq)
{
    int n = n0c + n1c;
    fill_chunk(As, Bs, a0, lda0, w0, lw0, tid);
    CP_COMMIT();
    for (int i = 0; i < n; i++) {
        int ip = i + 1;
        if (ip < n) {
            const float* A; const float* W; int lda, lw;
            if (ip < n0c) { A = a0 + ip * KB; lda = lda0; W = w0 + ip * KB; lw = lw0; }
            else { int ii = ip - n0c; A = a1 + ii * KB; lda = lda1; W = w1 + ii * KB; lw = lw1; }
            fill_chunk(As + (ip & 1) * 64, Bs + (ip & 1) * 32, A, lda, W, lw, tid);
            CP_COMMIT();
            CP_WAIT(1);
        } else {
            CP_WAIT(0);
        }
        __syncthreads();
        mma_compute(As + (i & 1) * 64, Bs + (i & 1) * 32, cacc, mrow, nw, l4, lq);
        __syncthreads();
    }
}

// ---------------- main persistent kernel ----------------
__global__ __launch_bounds__(256) void lstm_persist(
    const float* __restrict__ bih0, const float* __restrict__ bhh0,
    const float* __restrict__ bih1, const float* __restrict__ bhh1)
{
    extern __shared__ float smem_[];
    float (*As)[KPAD] = (float(*)[KPAD])smem_;                  // 128 rows (2 bufs x 64)
    float (*Bs)[KPAD] = (float(*)[KPAD])(smem_ + 128 * KPAD);   // 64 rows  (2 bufs x 32)
    float* bsum0 = smem_ + 192 * KPAD;
    float* bsum1 = bsum0 + 32;
    float (*cc0)[8] = (float(*)[8])(bsum1 + 32);                // 64 x 8
    float (*cc1)[8] = cc0 + 64;

    int tid = threadIdx.x, lane = tid & 31, w = tid >> 5;
    int mrow = (w & 3) * 16, nw = (w >> 2) * 16;
    int l4 = lane >> 2, lq = lane & 3;
    int d0 = blockIdx.x * 8;

    const float* W0h = g_W0h + (long)blockIdx.x * 32 * HH;
    const float* W0x = g_W0x + (long)blockIdx.x * 32 * IND;
    const float* W1i = g_W1i + (long)blockIdx.x * 32 * HH;
    const float* W1h = g_W1h + (long)blockIdx.x * 32 * HH;

    if (tid < 32) {
        int g = tid >> 3, j = tid & 7, n = (g << 10) + d0 + j;
        bsum0[tid] = bih0[n] + bhh0[n];
        bsum1[tid] = bih1[n] + bhh1[n];
    }
    {
        int i0 = tid * 2;
        ((float*)cc0)[i0] = 0.f; ((float*)cc0)[i0 + 1] = 0.f;
        ((float*)cc1)[i0] = 0.f; ((float*)cc1)[i0 + 1] = 0.f;
    }
    __syncthreads();

    for (int t = 0; t < TT; t++) {
        int p = t & 1;

        // ---- Phase A: layer 0  (gates = h0_prev@Whh0^T [+ x_{t-1}@Wih0^T]) ----
        float cA[2][4] = {};
        run_gemm(As, Bs,
                 g_h0p[p], HH, W0h, HH, HH / KB,
                 g_xp + (long)(t - 1) * BB * IND, IND, W0x, IND, (t > 0) ? IND / KB : 0,
                 cA, tid, mrow, nw, l4, lq);

        // gather gates into smem, apply cell
#pragma unroll
        for (int nt = 0; nt < 2; nt++) {
            int n0 = nw + nt * 8;
            As[mrow + l4][n0 + 2 * lq]         = cA[nt][0];
            As[mrow + l4][n0 + 2 * lq + 1]     = cA[nt][1];
            As[mrow + 8 + l4][n0 + 2 * lq]     = cA[nt][2];
            As[mrow + 8 + l4][n0 + 2 * lq + 1] = cA[nt][3];
        }
        __syncthreads();
#pragma unroll
        for (int s = 0; s < 2; s++) {
            int idx = tid * 2 + s, r = idx >> 3, j = idx & 7;
            float gi = As[r][j]      + bsum0[j];
            float gf = As[r][8 + j]  + bsum0[8 + j];
            float gg = As[r][16 + j] + bsum0[16 + j];
            float go = As[r][24 + j] + bsum0[24 + j];
            float c = sigm(gf) * cc0[r][j] + sigm(gi) * tanhf(gg);
            cc0[r][j] = c;
            g_h0p[p ^ 1][r * HH + d0 + kpos(j)] = tf32r(sigm(go) * tanhf(c));
        }
        grid_bar((unsigned)(2 * t + 1) * NCTA);

        // ---- Phase B: layer 1  (gates = h0_new@Wih1^T + h1_prev@Whh1^T) ----
        float cB[2][4] = {};
        run_gemm(As, Bs,
                 g_h0p[p ^ 1], HH, W1i, HH, HH / KB,
                 g_h1p[p],     HH, W1h, HH, HH / KB,
                 cB, tid, mrow, nw, l4, lq);

#pragma unroll
        for (int nt = 0; nt < 2; nt++) {
            int n0 = nw + nt * 8;
            As[mrow + l4][n0 + 2 * lq]         = cB[nt][0];
            As[mrow + l4][n0 + 2 * lq + 1]     = cB[nt][1];
            As[mrow + 8 + l4][n0 + 2 * lq]     = cB[nt][2];
            As[mrow + 8 + l4][n0 + 2 * lq + 1] = cB[nt][3];
        }
        __syncthreads();
#pragma unroll
        for (int s = 0; s < 2; s++) {
            int idx = tid * 2 + s, r = idx >> 3, j = idx & 7;
            float gi = As[r][j]      + bsum1[j];
            float gf = As[r][8 + j]  + bsum1[8 + j];
            float gg = As[r][16 + j] + bsum1[16 + j];
            float go = As[r][24 + j] + bsum1[24 + j];
            float c = sigm(gf) * cc1[r][j] + sigm(gi) * tanhf(gg);
            cc1[r][j] = c;
            float hv = tf32r(sigm(go) * tanhf(c));
            int pk = r * HH + d0 + kpos(j);
            g_h1p[p ^ 1][pk] = hv;
            g_h1all[(long)t * (BB * HH) + pk] = hv;
        }
        grid_bar((unsigned)(2 * t + 2) * NCTA);
    }
}

// ---------------- deferred output projection ----------------
__global__ __launch_bounds__(256) void out_kernel(
    const float* __restrict__ blin, float* __restrict__ out)
{
    extern __shared__ float smem_[];
    float (*As)[KPAD] = (float(*)[KPAD])smem_;
    float (*Bs)[KPAD] = (float(*)[KPAD])(smem_ + 128 * KPAD);

    int tid = threadIdx.x, lane = tid & 31, w = tid >> 5;
    int mrow = (w & 3) * 16, nw = (w >> 2) * 16;
    int l4 = lane >> 2, lq = lane & 3;
    int m0 = blockIdx.x * 64;
    int c0 = blockIdx.y * 32;

    float cO[2][4] = {};
    run_gemm(As, Bs,
             g_h1all + (long)m0 * HH, HH, g_Wlp + (long)blockIdx.y * 32 * HH, HH, HH / KB,
             (const float*)0, 0, (const float*)0, 0, 0,
             cO, tid, mrow, nw, l4, lq);

#pragma unroll
    for (int nt = 0; nt < 2; nt++) {
        int n0 = nw + nt * 8;
        int o0 = c0 + n0 + 2 * lq;
        int r0 = m0 + mrow + l4;
        int r1 = r0 + 8;
        int b0i = r0 & 63, t0i = r0 >> 6;
        int b1i = r1 & 63, t1i = r1 >> 6;
        out[(long)b0i * (TT * OUTD) + t0i * OUTD + o0]     = cO[nt][0] + blin[o0];
        out[(long)b0i * (TT * OUTD) + t0i * OUTD + o0 + 1] = cO[nt][1] + blin[o0 + 1];
        out[(long)b1i * (TT * OUTD) + t1i * OUTD + o0]     = cO[nt][2] + blin[o0];
        out[(long)b1i * (TT * OUTD) + t1i * OUTD + o0 + 1] = cO[nt][3] + blin[o0 + 1];
    }
}

// ---------------- host launcher ----------------
extern "C" void kernel_launch(void* const* d_in, const int* in_sizes, int n_in,
                              void* d_out, int out_size)
{
    const float* z    = (const float*)d_in[0];
    const float* x    = (const float*)d_in[1];
    const float* Wih0 = (const float*)d_in[2];
    const float* Whh0 = (const float*)d_in[3];
    const float* bih0 = (const float*)d_in[4];
    const float* bhh0 = (const float*)d_in[5];
    const float* Wih1 = (const float*)d_in[6];
    const float* Whh1 = (const float*)d_in[7];
    const float* bih1 = (const float*)d_in[8];
    const float* bhh1 = (const float*)d_in[9];
    const float* Wlin = (const float*)d_in[10];
    const float* blin = (const float*)d_in[11];
    float* out = (float*)d_out;

    const int SMEM_MAIN = (192 * KPAD + 64 + 1024) * 4;  // ~59.6 KB
    const int SMEM_OUT  = (192 * KPAD) * 4;              // ~55.3 KB
    cudaFuncSetAttribute(lstm_persist, cudaFuncAttributeMaxDynamicSharedMemorySize, SMEM_MAIN);
    cudaFuncSetAttribute(out_kernel,   cudaFuncAttributeMaxDynamicSharedMemorySize, SMEM_OUT);

    float* dW0h; cudaGetSymbolAddress((void**)&dW0h, g_W0h);
    float* dW0x; cudaGetSymbolAddress((void**)&dW0x, g_W0x);
    float* dW1i; cudaGetSymbolAddress((void**)&dW1i, g_W1i);
    float* dW1h; cudaGetSymbolAddress((void**)&dW1h, g_W1h);
    float* dWlp; cudaGetSymbolAddress((void**)&dWlp, g_Wlp);

    init_kernel<<<64, 1024>>>(z);
    pack_w<<<2048, 256>>>(Whh0, dW0h, HH, NCTA * 32 * HH);
    pack_w<<<1024, 256>>>(Wih0, dW0x, IND, NCTA * 32 * IND);
    pack_w<<<2048, 256>>>(Wih1, dW1i, HH, NCTA * 32 * HH);
    pack_w<<<2048, 256>>>(Whh1, dW1h, HH, NCTA * 32 * HH);
    pack_wl<<<256, 256>>>(Wlin, dWlp, HH, (OUTD / 32) * 32 * HH);
    pack_x<<<2048, 256>>>(x);

    lstm_persist<<<NCTA, 256, SMEM_MAIN>>>(bih0, bhh0, bih1, bhh1);
    out_kernel<<<dim3(TT * BB / 64, OUTD / 32), 256, SMEM_OUT>>>(blin, out);
}

// round 6
// speedup vs baseline: 3.5124x; 1.7712x over previous
#include <cuda_runtime.h>
#include <cuda_fp16.h>
#include <math.h>
#include <stdint.h>

#define BB   64
#define TT   512
#define IND  256
#define OUTD 256
#define HH   1024
#define NCTA 128
#define KB   128            // fp16 elements per K-chunk
#define KP16 144            // smem row stride in halfs (288B): conflict-free LDS.64 phases

// ---------------- persistent device state ----------------
__device__ __half   g_h0p[2][BB * HH];
__device__ __half   g_h1p[2][BB * HH];
__device__ __half   g_h1all[(long)TT * BB * HH];
__device__ __half   g_xp[(long)TT * BB * IND];
__device__ __half   g_W0h[NCTA * 32 * HH];
__device__ __half   g_W0x[NCTA * 32 * IND];
__device__ __half   g_W1i[NCTA * 32 * HH];
__device__ __half   g_W1h[NCTA * 32 * HH];
__device__ __half   g_Wlp[(OUTD / 32) * 32 * HH];
__device__ unsigned g_count;

// ---------------- helpers ----------------
__device__ __forceinline__ float sigm(float v) { return 1.f / (1.f + __expf(-v)); }

// k-permutation within each 16-group so a lane's mma quad (2q,2q+1,2q+8,2q+9)
// is contiguous: one LDS.64 yields (a0,a2) / (b0,b1).
__device__ __forceinline__ int kpos16(int k) {            // logical -> packed (within 16)
    int q = k >> 1, b = k & 1;
    return ((q & 3) << 2) | ((q >> 2) << 1) | b;
}
__device__ __forceinline__ int kinv16(int p) {            // packed -> logical (within 16)
    int b = p & 1, hi = (p >> 1) & 1, mid = (p >> 2) & 3;
    return 2 * (mid | (hi << 2)) + b;
}
__device__ __forceinline__ long pk_full(int k) {          // full packed index
    return (k & ~15) + kpos16(k & 15);
}

__device__ __forceinline__ void cp_async16(void* dst, const void* src) {
    uint32_t d = (uint32_t)__cvta_generic_to_shared(dst);
    asm volatile("cp.async.cg.shared.global [%0], [%1], 16;\n" :: "r"(d), "l"(src));
}
#define CP_COMMIT() asm volatile("cp.async.commit_group;\n" ::: "memory")
#define CP_WAIT(N)  asm volatile("cp.async.wait_group %0;\n" :: "n"(N) : "memory")

__device__ __forceinline__ unsigned ld_acq(const unsigned* p) {
    unsigned v;
    asm volatile("ld.acquire.gpu.global.u32 %0, [%1];" : "=r"(v) : "l"(p) : "memory");
    return v;
}

// Software grid barrier (release-fence writer, acquire-load spinner; h travels
// via L2 because tile fills use cp.async.cg which bypasses L1).
__device__ __forceinline__ void grid_bar(unsigned target) {
    __syncthreads();
    if (threadIdx.x == 0) {
        __threadfence();
        atomicAdd(&g_count, 1u);
        while (ld_acq(&g_count) < target) { }
    }
    __syncthreads();
}

// ---------------- init / pack kernels (one-time) ----------------
__global__ void init_kernel(const float* __restrict__ z) {
    int i = blockIdx.x * blockDim.x + threadIdx.x;       // over BB*HH
    int k = i & (HH - 1);
    long pk = (long)(i & ~(HH - 1)) + pk_full(k);
    __half v = __float2half_rn(z[i]);
    g_h0p[0][pk] = v;
    g_h1p[0][pk] = v;
    if (i == 0) g_count = 0u;
}

// Scatter-packed gate weights: dst[blk][c][kp] <- src[gate*1024 + blk*8 + (c&7)][k]
__global__ void pack_w(const float* __restrict__ src, __half* __restrict__ dst, int K, int total) {
    for (int i = blockIdx.x * blockDim.x + threadIdx.x; i < total; i += gridDim.x * blockDim.x) {
        int kp = i % K;
        int c  = (i / K) & 31;
        int blk = i / (K * 32);
        int k = (kp & ~15) + kinv16(kp & 15);
        int row = ((c >> 3) << 10) + (blk << 3) + (c & 7);
        dst[i] = __float2half_rn(src[(long)row * K + k]);
    }
}

// Plain packed weights (output projection): dst[blk][c][kp] <- src[blk*32+c][k]
__global__ void pack_wl(const float* __restrict__ src, __half* __restrict__ dst, int K, int total) {
    for (int i = blockIdx.x * blockDim.x + threadIdx.x; i < total; i += gridDim.x * blockDim.x) {
        int kp = i % K;
        int c  = (i / K) & 31;
        int blk = i / (K * 32);
        int k = (kp & ~15) + kinv16(kp & 15);
        dst[i] = __float2half_rn(src[(long)(blk * 32 + c) * K + k]);
    }
}

// x: [B][T][IN] -> packed fp16 [t][b][kp]
__global__ void pack_x(const float* __restrict__ x) {
    long total = (long)TT * BB * IND;
    for (long i = blockIdx.x * (long)blockDim.x + threadIdx.x; i < total;
         i += (long)gridDim.x * blockDim.x) {
        int kp = (int)(i % IND);
        int b  = (int)((i / IND) & 63);
        int t  = (int)(i / (IND * 64));
        int k = (kp & ~15) + kinv16(kp & 15);
        g_xp[i] = __float2half_rn(x[((long)b * TT + t) * IND + k]);
    }
}

// ---------------- GEMM building blocks ----------------
// Fill one chunk: A tile 64 x KB halfs (256B/row), B tile 32 x KB halfs.
__device__ __forceinline__ void fill_chunk(
    __half (*As)[KP16], __half (*Bs)[KP16],
    const __half* __restrict__ A, int ldA,
    const __half* __restrict__ W, int ldW, int tid)
{
#pragma unroll
    for (int it = 0; it < 4; it++) {                 // 1024 x 16B for A
        int idx = tid + it * 256;
        int row = idx >> 4;
        int seg = (idx & 15) << 3;                   // halfs
        cp_async16(&As[row][seg], A + (long)row * ldA + seg);
    }
#pragma unroll
    for (int it = 0; it < 2; it++) {                 // 512 x 16B for B
        int idx = tid + it * 256;
        int c   = idx >> 4;
        int seg = (idx & 15) << 3;
        cp_async16(&Bs[c][seg], W + (long)c * ldW + seg);
    }
}

// Compute one chunk: each warp m16n16 x kKB via fp16 mma m16n8k16, LDS.64 frags.
__device__ __forceinline__ void mma_compute(
    const __half (*As)[KP16], const __half (*Bs)[KP16],
    float cacc[2][4], int mrow, int nw, int l4, int lq)
{
#pragma unroll
    for (int g = 0; g < KB / 16; g++) {
        int off = g * 16 + 4 * lq;                   // packed quad for this lane
        uint2 va = *(const uint2*)&As[mrow + l4][off];        // (a0, a2)
        uint2 vb2 = *(const uint2*)&As[mrow + 8 + l4][off];   // (a1, a3)
#pragma unroll
        for (int nt = 0; nt < 2; nt++) {
            uint2 vb = *(const uint2*)&Bs[nw + nt * 8 + l4][off];  // (b0, b1)
            asm volatile(
                "mma.sync.aligned.m16n8k16.row.col.f32.f16.f16.f32 "
                "{%0,%1,%2,%3}, {%4,%5,%6,%7}, {%8,%9}, {%0,%1,%2,%3};"
                : "+f"(cacc[nt][0]), "+f"(cacc[nt][1]),
                  "+f"(cacc[nt][2]), "+f"(cacc[nt][3])
                : "r"(va.x), "r"(vb2.x), "r"(va.y), "r"(vb2.y),
                  "r"(vb.x), "r"(vb.y));
        }
    }
}

// Double-buffered pipelined GEMM over up to two (A, W) segments.
__device__ __forceinline__ void run_gemm(
    __half (*As)[KP16], __half (*Bs)[KP16],
    const __half* a0, int lda0, const __half* w0, int lw0, int n0c,
    const __half* a1, int lda1, const __half* w1, int lw1, int n1c,
    float cacc[2][4], int tid, int mrow, int nw, int l4, int lq)
{
    int n = n0c + n1c;
    fill_chunk(As, Bs, a0, lda0, w0, lw0, tid);
    CP_COMMIT();
    for (int i = 0; i < n; i++) {
        int ip = i + 1;
        if (ip < n) {
            const __half* A; const __half* W; int lda, lw;
            if (ip < n0c) { A = a0 + ip * KB; lda = lda0; W = w0 + ip * KB; lw = lw0; }
            else { int ii = ip - n0c; A = a1 + ii * KB; lda = lda1; W = w1 + ii * KB; lw = lw1; }
            fill_chunk(As + (ip & 1) * 64, Bs + (ip & 1) * 32, A, lda, W, lw, tid);
            CP_COMMIT();
            CP_WAIT(1);
        } else {
            CP_WAIT(0);
        }
        __syncthreads();
        mma_compute(As + (i & 1) * 64, Bs + (i & 1) * 32, cacc, mrow, nw, l4, lq);
        __syncthreads();
    }
}

// ---------------- main persistent kernel ----------------
__global__ __launch_bounds__(256) void lstm_persist(
    const float* __restrict__ bih0, const float* __restrict__ bhh0,
    const float* __restrict__ bih1, const float* __restrict__ bhh1)
{
    extern __shared__ __align__(16) unsigned char smraw[];
    __half (*As)[KP16] = (__half(*)[KP16])smraw;                         // 2 x 64 rows
    __half (*Bs)[KP16] = (__half(*)[KP16])(smraw + 128 * KP16 * 2);      // 2 x 32 rows
    float* fbase  = (float*)(smraw + 192 * KP16 * 2);
    float* bsum0  = fbase;
    float* bsum1  = fbase + 32;
    float (*cc0)[8] = (float(*)[8])(fbase + 64);                          // 64 x 8
    float (*cc1)[8] = cc0 + 64;
    float (*gs)[33] = (float(*)[33])smraw;                                // gate gather view (aliases As)

    int tid = threadIdx.x, lane = tid & 31, w = tid >> 5;
    int mrow = (w & 3) * 16, nw = (w >> 2) * 16;
    int l4 = lane >> 2, lq = lane & 3;
    int d0 = blockIdx.x * 8;

    const __half* W0h = g_W0h + (long)blockIdx.x * 32 * HH;
    const __half* W0x = g_W0x + (long)blockIdx.x * 32 * IND;
    const __half* W1i = g_W1i + (long)blockIdx.x * 32 * HH;
    const __half* W1h = g_W1h + (long)blockIdx.x * 32 * HH;

    if (tid < 32) {
        int g = tid >> 3, j = tid & 7, n = (g << 10) + d0 + j;
        bsum0[tid] = bih0[n] + bhh0[n];
        bsum1[tid] = bih1[n] + bhh1[n];
    }
    {
        int i0 = tid * 2;
        ((float*)cc0)[i0] = 0.f; ((float*)cc0)[i0 + 1] = 0.f;
        ((float*)cc1)[i0] = 0.f; ((float*)cc1)[i0 + 1] = 0.f;
    }
    __syncthreads();

    for (int t = 0; t < TT; t++) {
        int p = t & 1;

        // ---- Phase A: layer 0 ----
        float cA[2][4] = {};
        run_gemm(As, Bs,
                 g_h0p[p], HH, W0h, HH, HH / KB,
                 g_xp + (long)(t - 1) * BB * IND, IND, W0x, IND, (t > 0) ? IND / KB : 0,
                 cA, tid, mrow, nw, l4, lq);

#pragma unroll
        for (int nt = 0; nt < 2; nt++) {
            int n0 = nw + nt * 8;
            gs[mrow + l4][n0 + 2 * lq]         = cA[nt][0];
            gs[mrow + l4][n0 + 2 * lq + 1]     = cA[nt][1];
            gs[mrow + 8 + l4][n0 + 2 * lq]     = cA[nt][2];
            gs[mrow + 8 + l4][n0 + 2 * lq + 1] = cA[nt][3];
        }
        __syncthreads();
#pragma unroll
        for (int s = 0; s < 2; s++) {
            int idx = tid * 2 + s, r = idx >> 3, j = idx & 7;
            float gi = gs[r][j]      + bsum0[j];
            float gf = gs[r][8 + j]  + bsum0[8 + j];
            float gg = gs[r][16 + j] + bsum0[16 + j];
            float go = gs[r][24 + j] + bsum0[24 + j];
            float c = sigm(gf) * cc0[r][j] + sigm(gi) * tanhf(gg);
            cc0[r][j] = c;
            g_h0p[p ^ 1][(long)r * HH + pk_full(d0 + j)] = __float2half_rn(sigm(go) * tanhf(c));
        }
        grid_bar((unsigned)(2 * t + 1) * NCTA);

        // ---- Phase B: layer 1 ----
        float cB[2][4] = {};
        run_gemm(As, Bs,
                 g_h0p[p ^ 1], HH, W1i, HH, HH / KB,
                 g_h1p[p],     HH, W1h, HH, HH / KB,
                 cB, tid, mrow, nw, l4, lq);

#pragma unroll
        for (int nt = 0; nt < 2; nt++) {
            int n0 = nw + nt * 8;
            gs[mrow + l4][n0 + 2 * lq]         = cB[nt][0];
            gs[mrow + l4][n0 + 2 * lq + 1]     = cB[nt][1];
            gs[mrow + 8 + l4][n0 + 2 * lq]     = cB[nt][2];
            gs[mrow + 8 + l4][n0 + 2 * lq + 1] = cB[nt][3];
        }
        __syncthreads();
#pragma unroll
        for (int s = 0; s < 2; s++) {
            int idx = tid * 2 + s, r = idx >> 3, j = idx & 7;
            float gi = gs[r][j]      + bsum1[j];
            float gf = gs[r][8 + j]  + bsum1[8 + j];
            float gg = gs[r][16 + j] + bsum1[16 + j];
            float go = gs[r][24 + j] + bsum1[24 + j];
            float c = sigm(gf) * cc1[r][j] + sigm(gi) * tanhf(gg);
            cc1[r][j] = c;
            __half hv = __float2half_rn(sigm(go) * tanhf(c));
            long pk = (long)r * HH + pk_full(d0 + j);
            g_h1p[p ^ 1][pk] = hv;
            g_h1all[(long)t * (BB * HH) + pk] = hv;
        }
        grid_bar((unsigned)(2 * t + 2) * NCTA);
    }
}

// ---------------- deferred output projection ----------------
__global__ __launch_bounds__(256) void out_kernel(
    const float* __restrict__ blin, float* __restrict__ out)
{
    extern __shared__ __align__(16) unsigned char smraw[];
    __half (*As)[KP16] = (__half(*)[KP16])smraw;
    __half (*Bs)[KP16] = (__half(*)[KP16])(smraw + 128 * KP16 * 2);

    int tid = threadIdx.x, lane = tid & 31, w = tid >> 5;
    int mrow = (w & 3) * 16, nw = (w >> 2) * 16;
    int l4 = lane >> 2, lq = lane & 3;
    int m0 = blockIdx.x * 64;
    int c0 = blockIdx.y * 32;

    float cO[2][4] = {};
    run_gemm(As, Bs,
             g_h1all + (long)m0 * HH, HH, g_Wlp + (long)blockIdx.y * 32 * HH, HH, HH / KB,
             (const __half*)0, 0, (const __half*)0, 0, 0,
             cO, tid, mrow, nw, l4, lq);

#pragma unroll
    for (int nt = 0; nt < 2; nt++) {
        int n0 = nw + nt * 8;
        int o0 = c0 + n0 + 2 * lq;
        int r0 = m0 + mrow + l4;
        int r1 = r0 + 8;
        int b0i = r0 & 63, t0i = r0 >> 6;
        int b1i = r1 & 63, t1i = r1 >> 6;
        out[(long)b0i * (TT * OUTD) + t0i * OUTD + o0]     = cO[nt][0] + blin[o0];
        out[(long)b0i * (TT * OUTD) + t0i * OUTD + o0 + 1] = cO[nt][1] + blin[o0 + 1];
        out[(long)b1i * (TT * OUTD) + t1i * OUTD + o0]     = cO[nt][2] + blin[o0];
        out[(long)b1i * (TT * OUTD) + t1i * OUTD + o0 + 1] = cO[nt][3] + blin[o0 + 1];
    }
}

// ---------------- host launcher ----------------
extern "C" void kernel_launch(void* const* d_in, const int* in_sizes, int n_in,
                              void* d_out, int out_size)
{
    const float* z    = (const float*)d_in[0];
    const float* x    = (const float*)d_in[1];
    const float* Wih0 = (const float*)d_in[2];
    const float* Whh0 = (const float*)d_in[3];
    const float* bih0 = (const float*)d_in[4];
    const float* bhh0 = (const float*)d_in[5];
    const float* Wih1 = (const float*)d_in[6];
    const float* Whh1 = (const float*)d_in[7];
    const float* bih1 = (const float*)d_in[8];
    const float* bhh1 = (const float*)d_in[9];
    const float* Wlin = (const float*)d_in[10];
    const float* blin = (const float*)d_in[11];
    float* out = (float*)d_out;

    // smem: tiles (2*(64+32) rows * 288B) + biases(256B) + cell state(4KB)
    const int SMEM_TILES = 192 * KP16 * 2;           // 55296 B
    const int SMEM_MAIN  = SMEM_TILES + (64 + 1024) * 4;
    const int SMEM_OUT   = SMEM_TILES;
    cudaFuncSetAttribute(lstm_persist, cudaFuncAttributeMaxDynamicSharedMemorySize, SMEM_MAIN);
    cudaFuncSetAttribute(out_kernel,   cudaFuncAttributeMaxDynamicSharedMemorySize, SMEM_OUT);

    __half* dW0h; cudaGetSymbolAddress((void**)&dW0h, g_W0h);
    __half* dW0x; cudaGetSymbolAddress((void**)&dW0x, g_W0x);
    __half* dW1i; cudaGetSymbolAddress((void**)&dW1i, g_W1i);
    __half* dW1h; cudaGetSymbolAddress((void**)&dW1h, g_W1h);
    __half* dWlp; cudaGetSymbolAddress((void**)&dWlp, g_Wlp);

    init_kernel<<<64, 1024>>>(z);
    pack_w<<<2048, 256>>>(Whh0, dW0h, HH, NCTA * 32 * HH);
    pack_w<<<1024, 256>>>(Wih0, dW0x, IND, NCTA * 32 * IND);
    pack_w<<<2048, 256>>>(Wih1, dW1i, HH, NCTA * 32 * HH);
    pack_w<<<2048, 256>>>(Whh1, dW1h, HH, NCTA * 32 * HH);
    pack_wl<<<256, 256>>>(Wlin, dWlp, HH, (OUTD / 32) * 32 * HH);
    pack_x<<<2048, 256>>>(x);

    lstm_persist<<<NCTA, 256, SMEM_MAIN>>>(bih0, bhh0, bih1, bhh1);
    out_kernel<<<dim3(TT * BB / 64, OUTD / 32), 256, SMEM_OUT>>>(blin, out);
}